// round 1
// baseline (speedup 1.0000x reference)
#include <cuda_runtime.h>
#include <math.h>

#define NSMAX 100000
#define DIM   128
#define HID   512
#define KVOL  343

// ---- scratch (allocation-free rule: __device__ globals) ----
__device__ float g_xln[(size_t)NSMAX * DIM];    // LayerNorm output      [N,128]
__device__ float g_h[(size_t)NSMAX * HID];      // GELU(x@w1+b1)         [N,512]
__device__ float g_gsq[HID];                    // per-channel sum(x^2)
__device__ float g_scale[HID];                  // GRN scale: grn_g*nx + 1

// ============================================================
// 0. zero the GRN accumulator (must be re-zeroed every replay)
// ============================================================
__global__ void zero_gsq_kernel() {
    g_gsq[threadIdx.x] = 0.f;
}

// ============================================================
// 1. sparse depthwise conv + LayerNorm  (one block per site)
//    Compacts the ~8.4/343 valid neighbors with a DETERMINISTIC
//    prefix-sum (no atomic-ordering nondeterminism in the fp sum).
// ============================================================
__global__ __launch_bounds__(128)
void dw_ln_kernel(const float* __restrict__ feats,
                  const int*   __restrict__ nb,
                  const float* __restrict__ dw_w,
                  const float* __restrict__ dw_b,
                  const float* __restrict__ ln_g,
                  const float* __restrict__ ln_b,
                  int M) {
    int i   = blockIdx.x;
    int tid = threadIdx.x;
    int lane = tid & 31, wid = tid >> 5;

    __shared__ int   s_idx[KVOL];
    __shared__ int   s_k[KVOL];
    __shared__ int   s_wsum[4];
    __shared__ int   s_total;
    __shared__ float red[8];

    // gather my (up to 3) valid neighbor slots
    long base = (long)i * KVOL;
    int myi[3], myk[3];
    int cnt = 0;
    #pragma unroll
    for (int r = 0; r < 3; r++) {
        int j = tid + r * 128;
        if (j < KVOL) {
            int idx = nb[base + j];
            if (idx < M) { myi[cnt] = idx; myk[cnt] = j; cnt++; }
        }
    }
    // deterministic exclusive prefix over 128 threads
    int x = cnt;
    #pragma unroll
    for (int o = 1; o < 32; o <<= 1) {
        int y = __shfl_up_sync(0xffffffffu, x, o);
        if (lane >= o) x += y;
    }
    if (lane == 31) s_wsum[wid] = x;
    __syncthreads();
    int wbase = 0;
    for (int w = 0; w < wid; w++) wbase += s_wsum[w];
    int excl = wbase + x - cnt;
    for (int q = 0; q < cnt; q++) { s_idx[excl + q] = myi[q]; s_k[excl + q] = myk[q]; }
    if (tid == 127) s_total = excl + cnt;
    __syncthreads();

    // accumulate only valid neighbors (feats row reads are coalesced 512B)
    float acc = 0.f;
    int total = s_total;
    for (int p = 0; p < total; p++) {
        acc += feats[(long)s_idx[p] * DIM + tid] * dw_w[s_k[p] * DIM + tid];
    }
    acc += dw_b[tid];

    // LayerNorm over 128 channels (population variance, eps=1e-6)
    float s = acc, s2 = acc * acc;
    #pragma unroll
    for (int o = 16; o; o >>= 1) {
        s  += __shfl_xor_sync(0xffffffffu, s,  o);
        s2 += __shfl_xor_sync(0xffffffffu, s2, o);
    }
    if (lane == 0) { red[wid] = s; red[4 + wid] = s2; }
    __syncthreads();
    if (tid == 0) {
        float ts = red[0] + red[1] + red[2] + red[3];
        float t2 = red[4] + red[5] + red[6] + red[7];
        float mu  = ts * (1.f / DIM);
        float var = t2 * (1.f / DIM) - mu * mu;
        red[0] = mu;
        red[1] = rsqrtf(var + 1e-6f);
    }
    __syncthreads();
    float mu = red[0], rs = red[1];
    g_xln[(long)i * DIM + tid] = (acc - mu) * rs * ln_g[tid] + ln_b[tid];
}

// ============================================================
// 2. GEMM1: h = gelu(g_xln[M,128] @ w1[128,512] + b1)
//    epilogue also accumulates per-channel sum(h^2) into g_gsq.
//    Tiling: 128x64 block tile, BK=8, 256 thr, 8x4 per thread.
// ============================================================
__global__ __launch_bounds__(256)
void gemm1_kernel(const float* __restrict__ w1, const float* __restrict__ b1, int M) {
    __shared__ float As[8][132];   // transposed, padded
    __shared__ float Bs[8][64];
    __shared__ float bsum[64];

    int tid = threadIdx.x;
    int tx = tid & 15, ty = tid >> 4;
    int row0 = blockIdx.x * 128;
    int col0 = blockIdx.y * 64;

    float c[8][4];
    #pragma unroll
    for (int i = 0; i < 8; i++)
        #pragma unroll
        for (int j = 0; j < 4; j++) c[i][j] = 0.f;

    int arow  = tid >> 1;
    int acol4 = (tid & 1) * 4;
    int brow  = tid >> 5;
    int bcol  = (tid & 31) * 2;

    for (int k0 = 0; k0 < DIM; k0 += 8) {
        float4 av = make_float4(0.f, 0.f, 0.f, 0.f);
        int grow = row0 + arow;
        if (grow < M)
            av = *(const float4*)&g_xln[(long)grow * DIM + k0 + acol4];
        As[acol4 + 0][arow] = av.x;
        As[acol4 + 1][arow] = av.y;
        As[acol4 + 2][arow] = av.z;
        As[acol4 + 3][arow] = av.w;

        float2 bv = *(const float2*)&w1[(k0 + brow) * HID + col0 + bcol];
        Bs[brow][bcol]     = bv.x;
        Bs[brow][bcol + 1] = bv.y;
        __syncthreads();

        #pragma unroll
        for (int kk = 0; kk < 8; kk++) {
            float a[8], b[4];
            *(float4*)&a[0] = *(float4*)&As[kk][ty * 8];
            *(float4*)&a[4] = *(float4*)&As[kk][ty * 8 + 4];
            *(float4*)&b[0] = *(float4*)&Bs[kk][tx * 4];
            #pragma unroll
            for (int i = 0; i < 8; i++)
                #pragma unroll
                for (int j = 0; j < 4; j++)
                    c[i][j] += a[i] * b[j];
        }
        __syncthreads();
    }

    if (tid < 64) bsum[tid] = 0.f;
    __syncthreads();

    float bias[4];
    *(float4*)bias = *(const float4*)&b1[col0 + tx * 4];
    float ss[4] = {0.f, 0.f, 0.f, 0.f};
    #pragma unroll
    for (int i = 0; i < 8; i++) {
        int grow = row0 + ty * 8 + i;
        if (grow < M) {
            float4 gv;
            float* gp = &gv.x;
            #pragma unroll
            for (int j = 0; j < 4; j++) {
                float v = c[i][j] + bias[j];
                float g = 0.5f * v * (1.f + erff(v * 0.7071067811865475f));
                gp[j] = g;
                ss[j] += g * g;
            }
            *(float4*)&g_h[(long)grow * HID + col0 + tx * 4] = gv;
        }
    }
    #pragma unroll
    for (int j = 0; j < 4; j++) atomicAdd(&bsum[tx * 4 + j], ss[j]);
    __syncthreads();
    if (tid < 64) atomicAdd(&g_gsq[col0 + tid], bsum[tid]);
}

// ============================================================
// 3. GRN scale: gx=sqrt(gsq); nx=gx/(mean(gx)+eps); s=grn_g*nx+1
// ============================================================
__global__ void grn_kernel(const float* __restrict__ grn_g) {
    __shared__ float red[16];
    int c = threadIdx.x;  // 512 threads
    float gx = sqrtf(g_gsq[c]);
    float s = gx;
    #pragma unroll
    for (int o = 16; o; o >>= 1) s += __shfl_xor_sync(0xffffffffu, s, o);
    if ((c & 31) == 0) red[c >> 5] = s;
    __syncthreads();
    if (c == 0) {
        float t = 0.f;
        for (int w = 0; w < 16; w++) t += red[w];
        red[0] = t * (1.f / HID);
    }
    __syncthreads();
    float mean = red[0];
    float nx = gx / (mean + 1e-6f);
    g_scale[c] = grn_g[c] * nx + 1.f;
}

// ============================================================
// 4. GEMM2: out = (h*s + grn_b)[M,512] @ w2[512,128] + b2 + feats
//    (affine folded into the A-tile load)
// ============================================================
__global__ __launch_bounds__(256)
void gemm2_kernel(const float* __restrict__ w2, const float* __restrict__ b2,
                  const float* __restrict__ grn_b,
                  const float* __restrict__ feats,
                  float* __restrict__ out, int M) {
    __shared__ float As[8][132];
    __shared__ float Bs[8][64];

    int tid = threadIdx.x;
    int tx = tid & 15, ty = tid >> 4;
    int row0 = blockIdx.x * 128;
    int col0 = blockIdx.y * 64;

    float c[8][4];
    #pragma unroll
    for (int i = 0; i < 8; i++)
        #pragma unroll
        for (int j = 0; j < 4; j++) c[i][j] = 0.f;

    int arow  = tid >> 1;
    int acol4 = (tid & 1) * 4;
    int brow  = tid >> 5;
    int bcol  = (tid & 31) * 2;

    for (int k0 = 0; k0 < HID; k0 += 8) {
        float4 av = make_float4(0.f, 0.f, 0.f, 0.f);
        int grow = row0 + arow;
        if (grow < M) {
            av = *(const float4*)&g_h[(long)grow * HID + k0 + acol4];
            float4 sv = *(const float4*)&g_scale[k0 + acol4];
            float4 tv = *(const float4*)&grn_b[k0 + acol4];
            av.x = av.x * sv.x + tv.x;
            av.y = av.y * sv.y + tv.y;
            av.z = av.z * sv.z + tv.z;
            av.w = av.w * sv.w + tv.w;
        }
        As[acol4 + 0][arow] = av.x;
        As[acol4 + 1][arow] = av.y;
        As[acol4 + 2][arow] = av.z;
        As[acol4 + 3][arow] = av.w;

        float2 bv = *(const float2*)&w2[(k0 + brow) * DIM + col0 + bcol];
        Bs[brow][bcol]     = bv.x;
        Bs[brow][bcol + 1] = bv.y;
        __syncthreads();

        #pragma unroll
        for (int kk = 0; kk < 8; kk++) {
            float a[8], b[4];
            *(float4*)&a[0] = *(float4*)&As[kk][ty * 8];
            *(float4*)&a[4] = *(float4*)&As[kk][ty * 8 + 4];
            *(float4*)&b[0] = *(float4*)&Bs[kk][tx * 4];
            #pragma unroll
            for (int i = 0; i < 8; i++)
                #pragma unroll
                for (int j = 0; j < 4; j++)
                    c[i][j] += a[i] * b[j];
        }
        __syncthreads();
    }

    float bias[4];
    *(float4*)bias = *(const float4*)&b2[col0 + tx * 4];
    #pragma unroll
    for (int i = 0; i < 8; i++) {
        int grow = row0 + ty * 8 + i;
        if (grow < M) {
            float4 fv = *(const float4*)&feats[(long)grow * DIM + col0 + tx * 4];
            float4 ov;
            ov.x = c[i][0] + bias[0] + fv.x;
            ov.y = c[i][1] + bias[1] + fv.y;
            ov.z = c[i][2] + bias[2] + fv.z;
            ov.w = c[i][3] + bias[3] + fv.w;
            *(float4*)&out[(long)grow * DIM + col0 + tx * 4] = ov;
        }
    }
}

// ============================================================
extern "C" void kernel_launch(void* const* d_in, const int* in_sizes, int n_in,
                              void* d_out, int out_size) {
    const float* feats = (const float*)d_in[0];
    const int*   nb    = (const int*)d_in[1];
    const float* dw_w  = (const float*)d_in[2];
    const float* dw_b  = (const float*)d_in[3];
    const float* ln_g  = (const float*)d_in[4];
    const float* ln_b  = (const float*)d_in[5];
    const float* w1    = (const float*)d_in[6];
    const float* b1    = (const float*)d_in[7];
    const float* grn_g = (const float*)d_in[8];
    const float* grn_b = (const float*)d_in[9];
    const float* w2    = (const float*)d_in[10];
    const float* b2    = (const float*)d_in[11];
    float* out = (float*)d_out;
    int M = in_sizes[0] / DIM;

    zero_gsq_kernel<<<1, HID>>>();
    dw_ln_kernel<<<M, 128>>>(feats, nb, dw_w, dw_b, ln_g, ln_b, M);

    dim3 g1((M + 127) / 128, HID / 64);
    gemm1_kernel<<<g1, 256>>>(w1, b1, M);

    grn_kernel<<<1, HID>>>(grn_g);

    dim3 g2((M + 127) / 128, DIM / 64);
    gemm2_kernel<<<g2, 256>>>(w2, b2, grn_b, feats, out, M);
}

// round 7
// speedup vs baseline: 1.3051x; 1.3051x over previous
#include <cuda_runtime.h>
#include <math.h>
#include <cstdint>

#define NSMAX 100000
#define DIM   128
#define HID   512
#define KVOL  343

// ---- scratch (__device__ globals; no allocation allowed) ----
__device__ float g_xln[(size_t)NSMAX * DIM];   // LayerNorm output [N,128]
__device__ float g_h[(size_t)NSMAX * HID];     // GELU(x@w1+b1)    [N,512]
__device__ float g_b2p[DIM];                   // b2 + grn_b @ w2
__device__ float g_gsq[HID];                   // per-channel sum(h^2)
__device__ float g_scale[HID];                 // GRN scale: grn_g*nx + 1

// SMEM strides (words) chosen for conflict-free mma fragment loads
#define AST 132
#define BST 136
#define SMEM_WORDS (128 * AST + 128 * BST)     // 34304 words = 137216 B

__device__ __forceinline__ uint32_t f2tf(float f) {
    uint32_t u;
    asm("cvt.rna.tf32.f32 %0, %1;" : "=r"(u) : "f"(f));
    return u;
}

__device__ __forceinline__ void mma_tf32(float* c, const uint32_t* a, const uint32_t* b) {
    asm volatile(
        "mma.sync.aligned.m16n8k8.row.col.f32.tf32.tf32.f32 "
        "{%0,%1,%2,%3}, {%4,%5,%6,%7}, {%8,%9}, {%0,%1,%2,%3};"
        : "+f"(c[0]), "+f"(c[1]), "+f"(c[2]), "+f"(c[3])
        : "r"(a[0]), "r"(a[1]), "r"(a[2]), "r"(a[3]), "r"(b[0]), "r"(b[1]));
}

// ============================================================
// 0. zero GRN accumulator
// ============================================================
__global__ void zero_gsq_kernel() { g_gsq[threadIdx.x] = 0.f; }

// ============================================================
// 1. sparse depthwise conv + LayerNorm (validated in round 1)
// ============================================================
__global__ __launch_bounds__(128)
void dw_ln_kernel(const float* __restrict__ feats, const int* __restrict__ nb,
                  const float* __restrict__ dw_w, const float* __restrict__ dw_b,
                  const float* __restrict__ ln_g, const float* __restrict__ ln_b, int M) {
    int i = blockIdx.x, tid = threadIdx.x;
    int lane = tid & 31, wid = tid >> 5;
    __shared__ int s_idx[KVOL], s_k[KVOL], s_wsum[4], s_total;
    __shared__ float red[8];

    long base = (long)i * KVOL;
    int myi[3], myk[3], cnt = 0;
    #pragma unroll
    for (int r = 0; r < 3; r++) {
        int j = tid + r * 128;
        if (j < KVOL) {
            int idx = nb[base + j];
            if (idx < M) { myi[cnt] = idx; myk[cnt] = j; cnt++; }
        }
    }
    int x = cnt;
    #pragma unroll
    for (int o = 1; o < 32; o <<= 1) {
        int y = __shfl_up_sync(0xffffffffu, x, o);
        if (lane >= o) x += y;
    }
    if (lane == 31) s_wsum[wid] = x;
    __syncthreads();
    int wbase = 0;
    for (int w = 0; w < wid; w++) wbase += s_wsum[w];
    int excl = wbase + x - cnt;
    for (int q = 0; q < cnt; q++) { s_idx[excl + q] = myi[q]; s_k[excl + q] = myk[q]; }
    if (tid == 127) s_total = excl + cnt;
    __syncthreads();

    float acc = 0.f;
    int total = s_total;
    for (int p = 0; p < total; p++)
        acc += feats[(long)s_idx[p] * DIM + tid] * dw_w[s_k[p] * DIM + tid];
    acc += dw_b[tid];

    float s = acc, s2 = acc * acc;
    #pragma unroll
    for (int o = 16; o; o >>= 1) {
        s  += __shfl_xor_sync(0xffffffffu, s, o);
        s2 += __shfl_xor_sync(0xffffffffu, s2, o);
    }
    if (lane == 0) { red[wid] = s; red[4 + wid] = s2; }
    __syncthreads();
    if (tid == 0) {
        float ts = red[0] + red[1] + red[2] + red[3];
        float t2 = red[4] + red[5] + red[6] + red[7];
        float mu = ts * (1.f / DIM);
        float var = t2 * (1.f / DIM) - mu * mu;
        red[0] = mu; red[1] = rsqrtf(var + 1e-6f);
    }
    __syncthreads();
    float mu = red[0], rs = red[1];
    g_xln[(long)i * DIM + tid] = (acc - mu) * rs * ln_g[tid] + ln_b[tid];
}

// ============================================================
// 2. GEMM1 (mma.sync tf32): h = gelu(xln[M,128] @ w1[128,512] + b1)
//    epilogue fuses exact GELU + per-channel sum(h^2).
// ============================================================
__global__ __launch_bounds__(256)
void gemm1_mma(const float* __restrict__ w1, const float* __restrict__ b1, int M) {
    extern __shared__ uint32_t sm[];
    uint32_t* As = sm;                 // [128][AST]
    uint32_t* Bs = sm + 128 * AST;     // [128][BST]
    __shared__ float bsum[128];

    int t = threadIdx.x;
    int lane = t & 31, g = lane >> 2, tig = lane & 3;
    int warp_m = (t >> 5) & 1, warp_n = t >> 6;
    int row0 = blockIdx.x * 128, col0 = blockIdx.y * 128;

    // ---- fill A tile (128x128, tf32) ----
    #pragma unroll
    for (int i = 0; i < 16; i++) {
        int idx = t + i * 256, r = idx >> 5, c4 = idx & 31;
        float4 v = make_float4(0.f, 0.f, 0.f, 0.f);
        int gr = row0 + r;
        if (gr < M) v = *(const float4*)&g_xln[(long)gr * DIM + c4 * 4];
        uint4 u = make_uint4(f2tf(v.x), f2tf(v.y), f2tf(v.z), f2tf(v.w));
        *(uint4*)&As[r * AST + c4 * 4] = u;
    }
    // ---- fill B tile: Bs[k][n] = w1[k][col0+n] ----
    #pragma unroll
    for (int i = 0; i < 16; i++) {
        int idx = t + i * 256, k = idx >> 5, n4 = idx & 31;
        float4 v = *(const float4*)&w1[(long)k * HID + col0 + n4 * 4];
        uint4 u = make_uint4(f2tf(v.x), f2tf(v.y), f2tf(v.z), f2tf(v.w));
        *(uint4*)&Bs[k * BST + n4 * 4] = u;
    }
    __syncthreads();

    float c[4][4][4];
    #pragma unroll
    for (int mf = 0; mf < 4; mf++)
        #pragma unroll
        for (int nf = 0; nf < 4; nf++)
            #pragma unroll
            for (int j = 0; j < 4; j++) c[mf][nf][j] = 0.f;

    #pragma unroll 4
    for (int ks = 0; ks < 16; ks++) {
        int k = ks * 8;
        uint32_t a[4][4], b[4][2];
        #pragma unroll
        for (int mf = 0; mf < 4; mf++) {
            const uint32_t* ap = &As[(warp_m * 64 + mf * 16 + g) * AST + k + tig];
            a[mf][0] = ap[0];
            a[mf][1] = ap[8 * AST];
            a[mf][2] = ap[4];
            a[mf][3] = ap[8 * AST + 4];
        }
        #pragma unroll
        for (int nf = 0; nf < 4; nf++) {
            int cn = warp_n * 32 + nf * 8 + g;
            b[nf][0] = Bs[(k + tig) * BST + cn];
            b[nf][1] = Bs[(k + tig + 4) * BST + cn];
        }
        #pragma unroll
        for (int mf = 0; mf < 4; mf++)
            #pragma unroll
            for (int nf = 0; nf < 4; nf++)
                mma_tf32(c[mf][nf], a[mf], b[nf]);
    }

    // ---- epilogue: bias + exact GELU, store h, accumulate sum(h^2) ----
    float bn0[4], bn1[4], ss0[4], ss1[4];
    #pragma unroll
    for (int nf = 0; nf < 4; nf++) {
        int cn = col0 + warp_n * 32 + nf * 8 + 2 * tig;
        bn0[nf] = b1[cn]; bn1[nf] = b1[cn + 1];
        ss0[nf] = 0.f;    ss1[nf] = 0.f;
    }
    #pragma unroll
    for (int mf = 0; mf < 4; mf++) {
        #pragma unroll
        for (int half = 0; half < 2; half++) {
            int gr = row0 + warp_m * 64 + mf * 16 + g + half * 8;
            if (gr < M) {
                #pragma unroll
                for (int nf = 0; nf < 4; nf++) {
                    int cn = col0 + warp_n * 32 + nf * 8 + 2 * tig;
                    float v0 = c[mf][nf][half * 2 + 0] + bn0[nf];
                    float v1 = c[mf][nf][half * 2 + 1] + bn1[nf];
                    float h0 = 0.5f * v0 * (1.f + erff(v0 * 0.70710678118654752f));
                    float h1 = 0.5f * v1 * (1.f + erff(v1 * 0.70710678118654752f));
                    *(float2*)&g_h[(long)gr * HID + cn] = make_float2(h0, h1);
                    ss0[nf] += h0 * h0;
                    ss1[nf] += h1 * h1;
                }
            }
        }
    }
    if (t < 128) bsum[t] = 0.f;
    __syncthreads();
    #pragma unroll
    for (int nf = 0; nf < 4; nf++) {
        int cn = warp_n * 32 + nf * 8 + 2 * tig;
        atomicAdd(&bsum[cn], ss0[nf]);
        atomicAdd(&bsum[cn + 1], ss1[nf]);
    }
    __syncthreads();
    if (t < 128) atomicAdd(&g_gsq[col0 + t], bsum[t]);
}

// ============================================================
// 3. GRN scale: s[c] = grn_g[c] * (gx / (mean(gx)+eps)) + 1
// ============================================================
__global__ void grn_kernel(const float* __restrict__ grn_g) {
    __shared__ float red[16];
    int c = threadIdx.x;  // 512
    float gx = sqrtf(g_gsq[c]);
    float s = gx;
    #pragma unroll
    for (int o = 16; o; o >>= 1) s += __shfl_xor_sync(0xffffffffu, s, o);
    if ((c & 31) == 0) red[c >> 5] = s;
    __syncthreads();
    if (c == 0) {
        float tsum = 0.f;
        for (int w = 0; w < 16; w++) tsum += red[w];
        red[0] = tsum * (1.f / HID);
    }
    __syncthreads();
    float mean = red[0];
    g_scale[c] = grn_g[c] * (gx / (mean + 1e-6f)) + 1.f;
}

// ============================================================
// 3b. bias2' = b2 + grn_b @ w2
// ============================================================
__global__ void bias2p_kernel(const float* __restrict__ w2, const float* __restrict__ b2,
                              const float* __restrict__ grn_b) {
    __shared__ float part[4][DIM];
    int t = threadIdx.x;  // 512
    int j = t & 127, p = t >> 7;
    float acc = 0.f;
    #pragma unroll 4
    for (int k = p * 128; k < (p + 1) * 128; k++) acc += grn_b[k] * w2[k * DIM + j];
    part[p][j] = acc;
    __syncthreads();
    if (t < 128) g_b2p[t] = b2[t] + part[0][t] + part[1][t] + part[2][t] + part[3][t];
}

// ============================================================
// 4. GEMM2 (mma.sync tf32): out = h[M,512] @ (diag(s)w2) + bias2' + feats
//    GRN scale folded into the B-tile load. K=512 in 4 chunks.
// ============================================================
__global__ __launch_bounds__(256)
void gemm2_mma(const float* __restrict__ w2, const float* __restrict__ feats,
               float* __restrict__ out, int M) {
    extern __shared__ uint32_t sm[];
    uint32_t* As = sm;
    uint32_t* Bs = sm + 128 * AST;

    int t = threadIdx.x;
    int lane = t & 31, g = lane >> 2, tig = lane & 3;
    int warp_m = (t >> 5) & 1, warp_n = t >> 6;
    int row0 = blockIdx.x * 128;

    float c[4][4][4];
    #pragma unroll
    for (int mf = 0; mf < 4; mf++)
        #pragma unroll
        for (int nf = 0; nf < 4; nf++)
            #pragma unroll
            for (int j = 0; j < 4; j++) c[mf][nf][j] = 0.f;

    for (int cc = 0; cc < 4; cc++) {
        int k0 = cc * 128;
        if (cc > 0) __syncthreads();  // protect smem reuse
        // A chunk: h[row0.., k0..k0+127]
        #pragma unroll
        for (int i = 0; i < 16; i++) {
            int idx = t + i * 256, r = idx >> 5, c4 = idx & 31;
            float4 v = make_float4(0.f, 0.f, 0.f, 0.f);
            int gr = row0 + r;
            if (gr < M) v = *(const float4*)&g_h[(long)gr * HID + k0 + c4 * 4];
            uint4 u = make_uint4(f2tf(v.x), f2tf(v.y), f2tf(v.z), f2tf(v.w));
            *(uint4*)&As[r * AST + c4 * 4] = u;
        }
        // B chunk: Bs[k][n] = w2[k0+k][n] * s[k0+k]
        #pragma unroll
        for (int i = 0; i < 16; i++) {
            int idx = t + i * 256, k = idx >> 5, n4 = idx & 31;
            float sc = g_scale[k0 + k];
            float4 v = *(const float4*)&w2[(long)(k0 + k) * DIM + n4 * 4];
            uint4 u = make_uint4(f2tf(v.x * sc), f2tf(v.y * sc), f2tf(v.z * sc), f2tf(v.w * sc));
            *(uint4*)&Bs[k * BST + n4 * 4] = u;
        }
        __syncthreads();

        #pragma unroll 4
        for (int ks = 0; ks < 16; ks++) {
            int k = ks * 8;
            uint32_t a[4][4], b[4][2];
            #pragma unroll
            for (int mf = 0; mf < 4; mf++) {
                const uint32_t* ap = &As[(warp_m * 64 + mf * 16 + g) * AST + k + tig];
                a[mf][0] = ap[0];
                a[mf][1] = ap[8 * AST];
                a[mf][2] = ap[4];
                a[mf][3] = ap[8 * AST + 4];
            }
            #pragma unroll
            for (int nf = 0; nf < 4; nf++) {
                int cn = warp_n * 32 + nf * 8 + g;
                b[nf][0] = Bs[(k + tig) * BST + cn];
                b[nf][1] = Bs[(k + tig + 4) * BST + cn];
            }
            #pragma unroll
            for (int mf = 0; mf < 4; mf++)
                #pragma unroll
                for (int nf = 0; nf < 4; nf++)
                    mma_tf32(c[mf][nf], a[mf], b[nf]);
        }
    }

    // ---- epilogue: + bias2' + residual feats ----
    float bn0[4], bn1[4];
    #pragma unroll
    for (int nf = 0; nf < 4; nf++) {
        int cn = warp_n * 32 + nf * 8 + 2 * tig;
        bn0[nf] = g_b2p[cn]; bn1[nf] = g_b2p[cn + 1];
    }
    #pragma unroll
    for (int mf = 0; mf < 4; mf++) {
        #pragma unroll
        for (int half = 0; half < 2; half++) {
            int gr = row0 + warp_m * 64 + mf * 16 + g + half * 8;
            if (gr < M) {
                #pragma unroll
                for (int nf = 0; nf < 4; nf++) {
                    int cn = warp_n * 32 + nf * 8 + 2 * tig;
                    float2 fv = *(const float2*)&feats[(long)gr * DIM + cn];
                    float v0 = c[mf][nf][half * 2 + 0] + bn0[nf] + fv.x;
                    float v1 = c[mf][nf][half * 2 + 1] + bn1[nf] + fv.y;
                    *(float2*)&out[(long)gr * DIM + cn] = make_float2(v0, v1);
                }
            }
        }
    }
}

// ============================================================
extern "C" void kernel_launch(void* const* d_in, const int* in_sizes, int n_in,
                              void* d_out, int out_size) {
    const float* feats = (const float*)d_in[0];
    const int*   nb    = (const int*)d_in[1];
    const float* dw_w  = (const float*)d_in[2];
    const float* dw_b  = (const float*)d_in[3];
    const float* ln_g  = (const float*)d_in[4];
    const float* ln_b  = (const float*)d_in[5];
    const float* w1    = (const float*)d_in[6];
    const float* b1    = (const float*)d_in[7];
    const float* grn_g = (const float*)d_in[8];
    const float* grn_b = (const float*)d_in[9];
    const float* w2    = (const float*)d_in[10];
    const float* b2    = (const float*)d_in[11];
    float* out = (float*)d_out;
    int M = in_sizes[0] / DIM;

    static int s_attr_done = 0;
    if (!s_attr_done) {
        cudaFuncSetAttribute(gemm1_mma, cudaFuncAttributeMaxDynamicSharedMemorySize,
                             SMEM_WORDS * 4);
        cudaFuncSetAttribute(gemm2_mma, cudaFuncAttributeMaxDynamicSharedMemorySize,
                             SMEM_WORDS * 4);
        s_attr_done = 1;
    }

    zero_gsq_kernel<<<1, HID>>>();
    dw_ln_kernel<<<M, 128>>>(feats, nb, dw_w, dw_b, ln_g, ln_b, M);

    dim3 g1((M + 127) / 128, HID / 128);
    gemm1_mma<<<g1, 256, SMEM_WORDS * 4>>>(w1, b1, M);

    grn_kernel<<<1, HID>>>(grn_g);
    bias2p_kernel<<<1, HID>>>(w2, b2, grn_b);

    gemm2_mma<<<(M + 127) / 128, 256, SMEM_WORDS * 4>>>(w2, feats, out, M);
}

// round 12
// speedup vs baseline: 1.5181x; 1.1632x over previous
#include <cuda_runtime.h>
#include <cuda_fp16.h>
#include <math.h>
#include <cstdint>

#define NSMAX 100000
#define DIM   128
#define HID   512
#define KVOL  343

// ---- scratch (__device__ globals; no allocation allowed) ----
__device__ __half g_xln[(size_t)NSMAX * DIM];  // LayerNorm output (fp16) [N,128]
__device__ __half g_h[(size_t)NSMAX * HID];    // GELU(x@w1+b1)   (fp16) [N,512]
__device__ float  g_b2p[DIM];                  // b2 + grn_b @ w2
__device__ float  g_gsq[HID];                  // per-channel sum(h^2), fp32
__device__ float  g_scale[HID];                // GRN scale: grn_g*nx + 1

// SMEM halfword stride: 136 -> word stride 68 -> bank = 4g+tig (conflict-free)
#define ASTH 136
#define SMEM_BYTES (2 * 128 * ASTH * 2)        // A + B tiles, fp16 = 69632 B

__device__ __forceinline__ void mma_f16(float* c, const uint32_t* a, const uint32_t* b) {
    asm volatile(
        "mma.sync.aligned.m16n8k16.row.col.f32.f16.f16.f32 "
        "{%0,%1,%2,%3}, {%4,%5,%6,%7}, {%8,%9}, {%0,%1,%2,%3};"
        : "+f"(c[0]), "+f"(c[1]), "+f"(c[2]), "+f"(c[3])
        : "r"(a[0]), "r"(a[1]), "r"(a[2]), "r"(a[3]), "r"(b[0]), "r"(b[1]));
}

// ============================================================
// 0. zero GRN accumulator
// ============================================================
__global__ void zero_gsq_kernel() { g_gsq[threadIdx.x] = 0.f; }

// ============================================================
// 1. sparse depthwise conv + LayerNorm (validated) -> fp16 out
// ============================================================
__global__ __launch_bounds__(128)
void dw_ln_kernel(const float* __restrict__ feats, const int* __restrict__ nb,
                  const float* __restrict__ dw_w, const float* __restrict__ dw_b,
                  const float* __restrict__ ln_g, const float* __restrict__ ln_b, int M) {
    int i = blockIdx.x, tid = threadIdx.x;
    int lane = tid & 31, wid = tid >> 5;
    __shared__ int s_idx[KVOL], s_k[KVOL], s_wsum[4], s_total;
    __shared__ float red[8];

    long base = (long)i * KVOL;
    int myi[3], myk[3], cnt = 0;
    #pragma unroll
    for (int r = 0; r < 3; r++) {
        int j = tid + r * 128;
        if (j < KVOL) {
            int idx = nb[base + j];
            if (idx < M) { myi[cnt] = idx; myk[cnt] = j; cnt++; }
        }
    }
    int x = cnt;
    #pragma unroll
    for (int o = 1; o < 32; o <<= 1) {
        int y = __shfl_up_sync(0xffffffffu, x, o);
        if (lane >= o) x += y;
    }
    if (lane == 31) s_wsum[wid] = x;
    __syncthreads();
    int wbase = 0;
    for (int w = 0; w < wid; w++) wbase += s_wsum[w];
    int excl = wbase + x - cnt;
    for (int q = 0; q < cnt; q++) { s_idx[excl + q] = myi[q]; s_k[excl + q] = myk[q]; }
    if (tid == 127) s_total = excl + cnt;
    __syncthreads();

    float acc = 0.f;
    int total = s_total;
    for (int p = 0; p < total; p++)
        acc += feats[(long)s_idx[p] * DIM + tid] * dw_w[s_k[p] * DIM + tid];
    acc += dw_b[tid];

    float s = acc, s2 = acc * acc;
    #pragma unroll
    for (int o = 16; o; o >>= 1) {
        s  += __shfl_xor_sync(0xffffffffu, s, o);
        s2 += __shfl_xor_sync(0xffffffffu, s2, o);
    }
    if (lane == 0) { red[wid] = s; red[4 + wid] = s2; }
    __syncthreads();
    if (tid == 0) {
        float ts = red[0] + red[1] + red[2] + red[3];
        float t2 = red[4] + red[5] + red[6] + red[7];
        float mu = ts * (1.f / DIM);
        float var = t2 * (1.f / DIM) - mu * mu;
        red[0] = mu; red[1] = rsqrtf(var + 1e-6f);
    }
    __syncthreads();
    float mu = red[0], rs = red[1];
    g_xln[(long)i * DIM + tid] = __float2half_rn((acc - mu) * rs * ln_g[tid] + ln_b[tid]);
}

// ============================================================
// 2. GEMM1 (mma.sync f16): h = gelu(xln[M,128] @ w1[128,512] + b1)
//    fused exact GELU + per-channel sum(h^2); h stored fp16.
// ============================================================
__global__ __launch_bounds__(256, 2)
void gemm1_mma(const float* __restrict__ w1, const float* __restrict__ b1, int M) {
    extern __shared__ __half sh[];
    __half* Ah = sh;                    // [128][ASTH]
    __half* Bh = sh + 128 * ASTH;       // [128 n][ASTH k]
    const uint32_t* Aw = (const uint32_t*)Ah;
    const uint32_t* Bw = (const uint32_t*)Bh;
    __shared__ float bsum[128];

    int t = threadIdx.x;
    int lane = t & 31, g = lane >> 2, tig = lane & 3;
    int warp_m = (t >> 5) & 1, warp_n = t >> 6;
    int row0 = blockIdx.x * 128, col0 = blockIdx.y * 128;

    // ---- A tile: g_xln rows (fp16 copy, uint4 = 8 halfs) ----
    #pragma unroll
    for (int i = 0; i < 8; i++) {
        int idx = t + i * 256, r = idx >> 4, c8 = idx & 15;
        uint4 u = make_uint4(0u, 0u, 0u, 0u);
        int gr = row0 + r;
        if (gr < M) u = *(const uint4*)&g_xln[(long)gr * DIM + c8 * 8];
        *(uint4*)((uint32_t*)Ah + r * (ASTH / 2) + c8 * 4) = u;
    }
    // ---- B tile: Bh[n][k] = (half)w1[k][col0+n] ----
    #pragma unroll
    for (int i = 0; i < 16; i++) {
        int idx = t + i * 256, k = idx >> 5, n4 = idx & 31;
        float4 v = *(const float4*)&w1[(long)k * HID + col0 + n4 * 4];
        int nb = n4 * 4;
        Bh[(nb + 0) * ASTH + k] = __float2half_rn(v.x);
        Bh[(nb + 1) * ASTH + k] = __float2half_rn(v.y);
        Bh[(nb + 2) * ASTH + k] = __float2half_rn(v.z);
        Bh[(nb + 3) * ASTH + k] = __float2half_rn(v.w);
    }
    __syncthreads();

    float c[4][4][4];
    #pragma unroll
    for (int mf = 0; mf < 4; mf++)
        #pragma unroll
        for (int nf = 0; nf < 4; nf++)
            #pragma unroll
            for (int j = 0; j < 4; j++) c[mf][nf][j] = 0.f;

    #pragma unroll
    for (int ks = 0; ks < 8; ks++) {
        uint32_t a[4][4], b[4][2];
        #pragma unroll
        for (int mf = 0; mf < 4; mf++) {
            const uint32_t* ap = Aw + (warp_m * 64 + mf * 16 + g) * (ASTH / 2) + ks * 8 + tig;
            a[mf][0] = ap[0];
            a[mf][1] = ap[8 * (ASTH / 2)];
            a[mf][2] = ap[4];
            a[mf][3] = ap[8 * (ASTH / 2) + 4];
        }
        #pragma unroll
        for (int nf = 0; nf < 4; nf++) {
            const uint32_t* bp = Bw + (warp_n * 32 + nf * 8 + g) * (ASTH / 2) + ks * 8 + tig;
            b[nf][0] = bp[0];
            b[nf][1] = bp[4];
        }
        #pragma unroll
        for (int mf = 0; mf < 4; mf++)
            #pragma unroll
            for (int nf = 0; nf < 4; nf++)
                mma_f16(c[mf][nf], a[mf], b[nf]);
    }

    // ---- epilogue: bias + exact GELU, store fp16 h, accumulate sum(h^2) ----
    float bn0[4], bn1[4], ss0[4], ss1[4];
    #pragma unroll
    for (int nf = 0; nf < 4; nf++) {
        int cn = col0 + warp_n * 32 + nf * 8 + 2 * tig;
        bn0[nf] = b1[cn]; bn1[nf] = b1[cn + 1];
        ss0[nf] = 0.f;    ss1[nf] = 0.f;
    }
    #pragma unroll
    for (int mf = 0; mf < 4; mf++) {
        #pragma unroll
        for (int half = 0; half < 2; half++) {
            int gr = row0 + warp_m * 64 + mf * 16 + g + half * 8;
            if (gr < M) {
                #pragma unroll
                for (int nf = 0; nf < 4; nf++) {
                    int cn = col0 + warp_n * 32 + nf * 8 + 2 * tig;
                    float v0 = c[mf][nf][half * 2 + 0] + bn0[nf];
                    float v1 = c[mf][nf][half * 2 + 1] + bn1[nf];
                    float h0 = 0.5f * v0 * (1.f + erff(v0 * 0.70710678118654752f));
                    float h1 = 0.5f * v1 * (1.f + erff(v1 * 0.70710678118654752f));
                    *(__half2*)&g_h[(long)gr * HID + cn] = __floats2half2_rn(h0, h1);
                    ss0[nf] += h0 * h0;
                    ss1[nf] += h1 * h1;
                }
            }
        }
    }
    if (t < 128) bsum[t] = 0.f;
    __syncthreads();
    #pragma unroll
    for (int nf = 0; nf < 4; nf++) {
        int cn = warp_n * 32 + nf * 8 + 2 * tig;
        atomicAdd(&bsum[cn], ss0[nf]);
        atomicAdd(&bsum[cn + 1], ss1[nf]);
    }
    __syncthreads();
    if (t < 128) atomicAdd(&g_gsq[col0 + t], bsum[t]);
}

// ============================================================
// 3. GRN scale: s[c] = grn_g[c] * (gx / (mean(gx)+eps)) + 1
// ============================================================
__global__ void grn_kernel(const float* __restrict__ grn_g) {
    __shared__ float red[16];
    int c = threadIdx.x;  // 512
    float gx = sqrtf(g_gsq[c]);
    float s = gx;
    #pragma unroll
    for (int o = 16; o; o >>= 1) s += __shfl_xor_sync(0xffffffffu, s, o);
    if ((c & 31) == 0) red[c >> 5] = s;
    __syncthreads();
    if (c == 0) {
        float tsum = 0.f;
        for (int w = 0; w < 16; w++) tsum += red[w];
        red[0] = tsum * (1.f / HID);
    }
    __syncthreads();
    float mean = red[0];
    g_scale[c] = grn_g[c] * (gx / (mean + 1e-6f)) + 1.f;
}

// ============================================================
// 3b. bias2' = b2 + grn_b @ w2
// ============================================================
__global__ void bias2p_kernel(const float* __restrict__ w2, const float* __restrict__ b2,
                              const float* __restrict__ grn_b) {
    __shared__ float part[4][DIM];
    int t = threadIdx.x;  // 512
    int j = t & 127, p = t >> 7;
    float acc = 0.f;
    #pragma unroll 4
    for (int k = p * 128; k < (p + 1) * 128; k++) acc += grn_b[k] * w2[k * DIM + j];
    part[p][j] = acc;
    __syncthreads();
    if (t < 128) g_b2p[t] = b2[t] + part[0][t] + part[1][t] + part[2][t] + part[3][t];
}

// ============================================================
// 4. GEMM2 (mma.sync f16): out = h[M,512] @ (diag(s)w2) + bias2' + feats
//    GRN scale folded into the B-tile load. K=512 in 4 chunks.
// ============================================================
__global__ __launch_bounds__(256, 2)
void gemm2_mma(const float* __restrict__ w2, const float* __restrict__ feats,
               float* __restrict__ out, int M) {
    extern __shared__ __half sh[];
    __half* Ah = sh;
    __half* Bh = sh + 128 * ASTH;
    const uint32_t* Aw = (const uint32_t*)Ah;
    const uint32_t* Bw = (const uint32_t*)Bh;

    int t = threadIdx.x;
    int lane = t & 31, g = lane >> 2, tig = lane & 3;
    int warp_m = (t >> 5) & 1, warp_n = t >> 6;
    int row0 = blockIdx.x * 128;

    float c[4][4][4];
    #pragma unroll
    for (int mf = 0; mf < 4; mf++)
        #pragma unroll
        for (int nf = 0; nf < 4; nf++)
            #pragma unroll
            for (int j = 0; j < 4; j++) c[mf][nf][j] = 0.f;

    for (int cc = 0; cc < 4; cc++) {
        int k0 = cc * 128;
        if (cc > 0) __syncthreads();
        // A chunk: h rows (already fp16 — plain copy)
        #pragma unroll
        for (int i = 0; i < 8; i++) {
            int idx = t + i * 256, r = idx >> 4, c8 = idx & 15;
            uint4 u = make_uint4(0u, 0u, 0u, 0u);
            int gr = row0 + r;
            if (gr < M) u = *(const uint4*)&g_h[(long)gr * HID + k0 + c8 * 8];
            *(uint4*)((uint32_t*)Ah + r * (ASTH / 2) + c8 * 4) = u;
        }
        // B chunk: Bh[n][k] = (half)(w2[k0+k][n] * s[k0+k])
        #pragma unroll
        for (int i = 0; i < 16; i++) {
            int idx = t + i * 256, k = idx >> 5, n4 = idx & 31;
            float sc = g_scale[k0 + k];
            float4 v = *(const float4*)&w2[(long)(k0 + k) * DIM + n4 * 4];
            int nb = n4 * 4;
            Bh[(nb + 0) * ASTH + k] = __float2half_rn(v.x * sc);
            Bh[(nb + 1) * ASTH + k] = __float2half_rn(v.y * sc);
            Bh[(nb + 2) * ASTH + k] = __float2half_rn(v.z * sc);
            Bh[(nb + 3) * ASTH + k] = __float2half_rn(v.w * sc);
        }
        __syncthreads();

        #pragma unroll
        for (int ks = 0; ks < 8; ks++) {
            uint32_t a[4][4], b[4][2];
            #pragma unroll
            for (int mf = 0; mf < 4; mf++) {
                const uint32_t* ap = Aw + (warp_m * 64 + mf * 16 + g) * (ASTH / 2) + ks * 8 + tig;
                a[mf][0] = ap[0];
                a[mf][1] = ap[8 * (ASTH / 2)];
                a[mf][2] = ap[4];
                a[mf][3] = ap[8 * (ASTH / 2) + 4];
            }
            #pragma unroll
            for (int nf = 0; nf < 4; nf++) {
                const uint32_t* bp = Bw + (warp_n * 32 + nf * 8 + g) * (ASTH / 2) + ks * 8 + tig;
                b[nf][0] = bp[0];
                b[nf][1] = bp[4];
            }
            #pragma unroll
            for (int mf = 0; mf < 4; mf++)
                #pragma unroll
                for (int nf = 0; nf < 4; nf++)
                    mma_f16(c[mf][nf], a[mf], b[nf]);
        }
    }

    // ---- epilogue: + bias2' + residual feats ----
    float bn0[4], bn1[4];
    #pragma unroll
    for (int nf = 0; nf < 4; nf++) {
        int cn = warp_n * 32 + nf * 8 + 2 * tig;
        bn0[nf] = g_b2p[cn]; bn1[nf] = g_b2p[cn + 1];
    }
    #pragma unroll
    for (int mf = 0; mf < 4; mf++) {
        #pragma unroll
        for (int half = 0; half < 2; half++) {
            int gr = row0 + warp_m * 64 + mf * 16 + g + half * 8;
            if (gr < M) {
                #pragma unroll
                for (int nf = 0; nf < 4; nf++) {
                    int cn = warp_n * 32 + nf * 8 + 2 * tig;
                    float2 fv = *(const float2*)&feats[(long)gr * DIM + cn];
                    float v0 = c[mf][nf][half * 2 + 0] + bn0[nf] + fv.x;
                    float v1 = c[mf][nf][half * 2 + 1] + bn1[nf] + fv.y;
                    *(float2*)&out[(long)gr * DIM + cn] = make_float2(v0, v1);
                }
            }
        }
    }
}

// ============================================================
extern "C" void kernel_launch(void* const* d_in, const int* in_sizes, int n_in,
                              void* d_out, int out_size) {
    const float* feats = (const float*)d_in[0];
    const int*   nb    = (const int*)d_in[1];
    const float* dw_w  = (const float*)d_in[2];
    const float* dw_b  = (const float*)d_in[3];
    const float* ln_g  = (const float*)d_in[4];
    const float* ln_b  = (const float*)d_in[5];
    const float* w1    = (const float*)d_in[6];
    const float* b1    = (const float*)d_in[7];
    const float* grn_g = (const float*)d_in[8];
    const float* grn_b = (const float*)d_in[9];
    const float* w2    = (const float*)d_in[10];
    const float* b2    = (const float*)d_in[11];
    float* out = (float*)d_out;
    int M = in_sizes[0] / DIM;

    static int s_attr_done = 0;
    if (!s_attr_done) {
        cudaFuncSetAttribute(gemm1_mma, cudaFuncAttributeMaxDynamicSharedMemorySize, SMEM_BYTES);
        cudaFuncSetAttribute(gemm2_mma, cudaFuncAttributeMaxDynamicSharedMemorySize, SMEM_BYTES);
        s_attr_done = 1;
    }

    zero_gsq_kernel<<<1, HID>>>();
    dw_ln_kernel<<<M, 128>>>(feats, nb, dw_w, dw_b, ln_g, ln_b, M);

    dim3 g1((M + 127) / 128, HID / 128);
    gemm1_mma<<<g1, 256, SMEM_BYTES>>>(w1, b1, M);

    grn_kernel<<<1, HID>>>(grn_g);
    bias2p_kernel<<<1, HID>>>(w2, b2, grn_b);

    gemm2_mma<<<(M + 127) / 128, 256, SMEM_BYTES>>>(w2, feats, out, M);
}

// round 14
// speedup vs baseline: 2.1983x; 1.4481x over previous
#include <cuda_runtime.h>
#include <cuda_fp16.h>
#include <math.h>
#include <cstdint>

#define NSMAX 100000
#define DIM   128
#define HID   512
#define KVOL  343

// ---- scratch (__device__ globals; no allocation allowed) ----
__device__ __half g_xln[(size_t)NSMAX * DIM];  // LayerNorm output (fp16) [N,128]
__device__ __half g_h[(size_t)NSMAX * HID];    // GELU(x@w1+b1)   (fp16) [N,512]
__device__ __half g_w1h[(size_t)HID * DIM];    // w1^T fp16, n-major [512][128]
__device__ __half g_w2h[(size_t)DIM * HID];    // (diag(s)w2)^T fp16 [128][512]
__device__ float  g_b2p[DIM];                  // b2 + grn_b @ w2
__device__ float  g_gsq[HID];                  // per-channel sum(h^2), fp32
__device__ float  g_scale[HID];                // GRN scale: grn_g*nx + 1

// SMEM halfword stride: 136 -> word stride 68 -> bank = 4g+tig (conflict-free)
#define ASTH 136
#define SMEM_BYTES (2 * 128 * ASTH * 2)        // A + B tiles, fp16 = 69632 B

__device__ __forceinline__ void mma_f16(float* c, const uint32_t* a, const uint32_t* b) {
    asm volatile(
        "mma.sync.aligned.m16n8k16.row.col.f32.f16.f16.f32 "
        "{%0,%1,%2,%3}, {%4,%5,%6,%7}, {%8,%9}, {%0,%1,%2,%3};"
        : "+f"(c[0]), "+f"(c[1]), "+f"(c[2]), "+f"(c[3])
        : "r"(a[0]), "r"(a[1]), "r"(a[2]), "r"(a[3]), "r"(b[0]), "r"(b[1]));
}

// ============================================================
// 0. zero GRN accumulator
// ============================================================
__global__ void zero_gsq_kernel() { g_gsq[threadIdx.x] = 0.f; }

// ============================================================
// 0b. w1 -> fp16 n-major transpose: g_w1h[n][k] = w1[k][n]
// ============================================================
__global__ void w1h_kernel(const float* __restrict__ w1) {
    __shared__ float s[32][33];
    int n0 = blockIdx.x * 32, k0 = blockIdx.y * 32;
    int tx = threadIdx.x, ty = threadIdx.y;  // (32,8)
    #pragma unroll
    for (int j = 0; j < 32; j += 8) s[ty + j][tx] = w1[(long)(k0 + ty + j) * HID + n0 + tx];
    __syncthreads();
    #pragma unroll
    for (int j = 0; j < 32; j += 8)
        g_w1h[(long)(n0 + ty + j) * DIM + k0 + tx] = __float2half_rn(s[tx][ty + j]);
}

// ============================================================
// 1. sparse depthwise conv + LayerNorm (validated) -> fp16 out
// ============================================================
__global__ __launch_bounds__(128)
void dw_ln_kernel(const float* __restrict__ feats, const int* __restrict__ nb,
                  const float* __restrict__ dw_w, const float* __restrict__ dw_b,
                  const float* __restrict__ ln_g, const float* __restrict__ ln_b, int M) {
    int i = blockIdx.x, tid = threadIdx.x;
    int lane = tid & 31, wid = tid >> 5;
    __shared__ int s_idx[KVOL], s_k[KVOL], s_wsum[4], s_total;
    __shared__ float red[8];

    long base = (long)i * KVOL;
    int myi[3], myk[3], cnt = 0;
    #pragma unroll
    for (int r = 0; r < 3; r++) {
        int j = tid + r * 128;
        if (j < KVOL) {
            int idx = nb[base + j];
            if (idx < M) { myi[cnt] = idx; myk[cnt] = j; cnt++; }
        }
    }
    int x = cnt;
    #pragma unroll
    for (int o = 1; o < 32; o <<= 1) {
        int y = __shfl_up_sync(0xffffffffu, x, o);
        if (lane >= o) x += y;
    }
    if (lane == 31) s_wsum[wid] = x;
    __syncthreads();
    int wbase = 0;
    for (int w = 0; w < wid; w++) wbase += s_wsum[w];
    int excl = wbase + x - cnt;
    for (int q = 0; q < cnt; q++) { s_idx[excl + q] = myi[q]; s_k[excl + q] = myk[q]; }
    if (tid == 127) s_total = excl + cnt;
    __syncthreads();

    float acc = 0.f;
    int total = s_total;
    for (int p = 0; p < total; p++)
        acc += feats[(long)s_idx[p] * DIM + tid] * dw_w[s_k[p] * DIM + tid];
    acc += dw_b[tid];

    float s = acc, s2 = acc * acc;
    #pragma unroll
    for (int o = 16; o; o >>= 1) {
        s  += __shfl_xor_sync(0xffffffffu, s, o);
        s2 += __shfl_xor_sync(0xffffffffu, s2, o);
    }
    if (lane == 0) { red[wid] = s; red[4 + wid] = s2; }
    __syncthreads();
    if (tid == 0) {
        float ts = red[0] + red[1] + red[2] + red[3];
        float t2 = red[4] + red[5] + red[6] + red[7];
        float mu = ts * (1.f / DIM);
        float var = t2 * (1.f / DIM) - mu * mu;
        red[0] = mu; red[1] = rsqrtf(var + 1e-6f);
    }
    __syncthreads();
    float mu = red[0], rs = red[1];
    g_xln[(long)i * DIM + tid] = __float2half_rn((acc - mu) * rs * ln_g[tid] + ln_b[tid]);
}

// ============================================================
// 2. GEMM1 (mma.sync f16): h = gelu(xln[M,128] @ w1[128,512] + b1)
//    conflict-free vectorized tile fills from precomputed fp16 weights.
// ============================================================
__global__ __launch_bounds__(256, 2)
void gemm1_mma(const float* __restrict__ b1, int M) {
    extern __shared__ __half sh[];
    __half* Ah = sh;                    // [128 m][ASTH k]
    __half* Bh = sh + 128 * ASTH;       // [128 n][ASTH k]
    const uint32_t* Aw = (const uint32_t*)Ah;
    const uint32_t* Bw = (const uint32_t*)Bh;
    __shared__ float bsum[128];

    int t = threadIdx.x;
    int lane = t & 31, g = lane >> 2, tig = lane & 3;
    int warp_m = (t >> 5) & 1, warp_n = t >> 6;
    int row0 = blockIdx.x * 128, col0 = blockIdx.y * 128;

    // ---- A tile: g_xln rows (uint4 = 8 halfs, conflict-free) ----
    #pragma unroll
    for (int i = 0; i < 8; i++) {
        int idx = t + i * 256, r = idx >> 4, c8 = idx & 15;
        uint4 u = make_uint4(0u, 0u, 0u, 0u);
        int gr = row0 + r;
        if (gr < M) u = *(const uint4*)&g_xln[(long)gr * DIM + c8 * 8];
        *(uint4*)((uint32_t*)Ah + r * (ASTH / 2) + c8 * 4) = u;
    }
    // ---- B tile: rows of g_w1h (uint4 copies, conflict-free) ----
    #pragma unroll
    for (int i = 0; i < 8; i++) {
        int idx = t + i * 256, n = idx >> 4, c8 = idx & 15;
        uint4 u = *(const uint4*)&g_w1h[(long)(col0 + n) * DIM + c8 * 8];
        *(uint4*)((uint32_t*)Bh + n * (ASTH / 2) + c8 * 4) = u;
    }
    __syncthreads();

    float c[4][4][4];
    #pragma unroll
    for (int mf = 0; mf < 4; mf++)
        #pragma unroll
        for (int nf = 0; nf < 4; nf++)
            #pragma unroll
            for (int j = 0; j < 4; j++) c[mf][nf][j] = 0.f;

    #pragma unroll
    for (int ks = 0; ks < 8; ks++) {
        uint32_t a[4][4], b[4][2];
        #pragma unroll
        for (int mf = 0; mf < 4; mf++) {
            const uint32_t* ap = Aw + (warp_m * 64 + mf * 16 + g) * (ASTH / 2) + ks * 8 + tig;
            a[mf][0] = ap[0];
            a[mf][1] = ap[8 * (ASTH / 2)];
            a[mf][2] = ap[4];
            a[mf][3] = ap[8 * (ASTH / 2) + 4];
        }
        #pragma unroll
        for (int nf = 0; nf < 4; nf++) {
            const uint32_t* bp = Bw + (warp_n * 32 + nf * 8 + g) * (ASTH / 2) + ks * 8 + tig;
            b[nf][0] = bp[0];
            b[nf][1] = bp[4];
        }
        #pragma unroll
        for (int mf = 0; mf < 4; mf++)
            #pragma unroll
            for (int nf = 0; nf < 4; nf++)
                mma_f16(c[mf][nf], a[mf], b[nf]);
    }

    // ---- epilogue: bias + exact GELU, store fp16 h, accumulate sum(h^2) ----
    float bn0[4], bn1[4], ss0[4], ss1[4];
    #pragma unroll
    for (int nf = 0; nf < 4; nf++) {
        int cn = col0 + warp_n * 32 + nf * 8 + 2 * tig;
        bn0[nf] = b1[cn]; bn1[nf] = b1[cn + 1];
        ss0[nf] = 0.f;    ss1[nf] = 0.f;
    }
    #pragma unroll
    for (int mf = 0; mf < 4; mf++) {
        #pragma unroll
        for (int half = 0; half < 2; half++) {
            int gr = row0 + warp_m * 64 + mf * 16 + g + half * 8;
            if (gr < M) {
                #pragma unroll
                for (int nf = 0; nf < 4; nf++) {
                    int cn = col0 + warp_n * 32 + nf * 8 + 2 * tig;
                    float v0 = c[mf][nf][half * 2 + 0] + bn0[nf];
                    float v1 = c[mf][nf][half * 2 + 1] + bn1[nf];
                    float h0 = 0.5f * v0 * (1.f + erff(v0 * 0.70710678118654752f));
                    float h1 = 0.5f * v1 * (1.f + erff(v1 * 0.70710678118654752f));
                    *(__half2*)&g_h[(long)gr * HID + cn] = __floats2half2_rn(h0, h1);
                    ss0[nf] += h0 * h0;
                    ss1[nf] += h1 * h1;
                }
            }
        }
    }
    if (t < 128) bsum[t] = 0.f;
    __syncthreads();
    #pragma unroll
    for (int nf = 0; nf < 4; nf++) {
        int cn = warp_n * 32 + nf * 8 + 2 * tig;
        atomicAdd(&bsum[cn], ss0[nf]);
        atomicAdd(&bsum[cn + 1], ss1[nf]);
    }
    __syncthreads();
    if (t < 128) atomicAdd(&g_gsq[col0 + t], bsum[t]);
}

// ============================================================
// 3. GRN scale: s[c] = grn_g[c] * (gx / (mean(gx)+eps)) + 1
// ============================================================
__global__ void grn_kernel(const float* __restrict__ grn_g) {
    __shared__ float red[16];
    int c = threadIdx.x;  // 512
    float gx = sqrtf(g_gsq[c]);
    float s = gx;
    #pragma unroll
    for (int o = 16; o; o >>= 1) s += __shfl_xor_sync(0xffffffffu, s, o);
    if ((c & 31) == 0) red[c >> 5] = s;
    __syncthreads();
    if (c == 0) {
        float tsum = 0.f;
        for (int w = 0; w < 16; w++) tsum += red[w];
        red[0] = tsum * (1.f / HID);
    }
    __syncthreads();
    float mean = red[0];
    g_scale[c] = grn_g[c] * (gx / (mean + 1e-6f)) + 1.f;
}

// ============================================================
// 3b. w2 -> fp16 n-major with GRN scale: g_w2h[n][k] = w2[k][n]*s[k]
// ============================================================
__global__ void w2h_kernel(const float* __restrict__ w2) {
    __shared__ float s[32][33];
    int n0 = blockIdx.x * 32, k0 = blockIdx.y * 32;
    int tx = threadIdx.x, ty = threadIdx.y;  // (32,8)
    #pragma unroll
    for (int j = 0; j < 32; j += 8) s[ty + j][tx] = w2[(long)(k0 + ty + j) * DIM + n0 + tx];
    __syncthreads();
    #pragma unroll
    for (int j = 0; j < 32; j += 8)
        g_w2h[(long)(n0 + ty + j) * HID + k0 + tx] =
            __float2half_rn(s[tx][ty + j] * g_scale[k0 + tx]);
}

// ============================================================
// 3c. bias2' = b2 + grn_b @ w2
// ============================================================
__global__ void bias2p_kernel(const float* __restrict__ w2, const float* __restrict__ b2,
                              const float* __restrict__ grn_b) {
    __shared__ float part[4][DIM];
    int t = threadIdx.x;  // 512
    int j = t & 127, p = t >> 7;
    float acc = 0.f;
    #pragma unroll 4
    for (int k = p * 128; k < (p + 1) * 128; k++) acc += grn_b[k] * w2[k * DIM + j];
    part[p][j] = acc;
    __syncthreads();
    if (t < 128) g_b2p[t] = b2[t] + part[0][t] + part[1][t] + part[2][t] + part[3][t];
}

// ============================================================
// 4. GEMM2 (mma.sync f16): out = h[M,512] @ (diag(s)w2) + bias2' + feats
//    K=512 in 4 chunks; conflict-free vectorized fills.
// ============================================================
__global__ __launch_bounds__(256, 2)
void gemm2_mma(const float* __restrict__ feats, float* __restrict__ out, int M) {
    extern __shared__ __half sh[];
    __half* Ah = sh;
    __half* Bh = sh + 128 * ASTH;
    const uint32_t* Aw = (const uint32_t*)Ah;
    const uint32_t* Bw = (const uint32_t*)Bh;

    int t = threadIdx.x;
    int lane = t & 31, g = lane >> 2, tig = lane & 3;
    int warp_m = (t >> 5) & 1, warp_n = t >> 6;
    int row0 = blockIdx.x * 128;

    float c[4][4][4];
    #pragma unroll
    for (int mf = 0; mf < 4; mf++)
        #pragma unroll
        for (int nf = 0; nf < 4; nf++)
            #pragma unroll
            for (int j = 0; j < 4; j++) c[mf][nf][j] = 0.f;

    for (int cc = 0; cc < 4; cc++) {
        int k0 = cc * 128;
        if (cc > 0) __syncthreads();
        // A chunk: h rows (fp16 uint4 copy)
        #pragma unroll
        for (int i = 0; i < 8; i++) {
            int idx = t + i * 256, r = idx >> 4, c8 = idx & 15;
            uint4 u = make_uint4(0u, 0u, 0u, 0u);
            int gr = row0 + r;
            if (gr < M) u = *(const uint4*)&g_h[(long)gr * HID + k0 + c8 * 8];
            *(uint4*)((uint32_t*)Ah + r * (ASTH / 2) + c8 * 4) = u;
        }
        // B chunk: rows of g_w2h (uint4 copy, conflict-free)
        #pragma unroll
        for (int i = 0; i < 8; i++) {
            int idx = t + i * 256, n = idx >> 4, c8 = idx & 15;
            uint4 u = *(const uint4*)&g_w2h[(long)n * HID + k0 + c8 * 8];
            *(uint4*)((uint32_t*)Bh + n * (ASTH / 2) + c8 * 4) = u;
        }
        __syncthreads();

        #pragma unroll
        for (int ks = 0; ks < 8; ks++) {
            uint32_t a[4][4], b[4][2];
            #pragma unroll
            for (int mf = 0; mf < 4; mf++) {
                const uint32_t* ap = Aw + (warp_m * 64 + mf * 16 + g) * (ASTH / 2) + ks * 8 + tig;
                a[mf][0] = ap[0];
                a[mf][1] = ap[8 * (ASTH / 2)];
                a[mf][2] = ap[4];
                a[mf][3] = ap[8 * (ASTH / 2) + 4];
            }
            #pragma unroll
            for (int nf = 0; nf < 4; nf++) {
                const uint32_t* bp = Bw + (warp_n * 32 + nf * 8 + g) * (ASTH / 2) + ks * 8 + tig;
                b[nf][0] = bp[0];
                b[nf][1] = bp[4];
            }
            #pragma unroll
            for (int mf = 0; mf < 4; mf++)
                #pragma unroll
                for (int nf = 0; nf < 4; nf++)
                    mma_f16(c[mf][nf], a[mf], b[nf]);
        }
    }

    // ---- epilogue: + bias2' + residual feats ----
    float bn0[4], bn1[4];
    #pragma unroll
    for (int nf = 0; nf < 4; nf++) {
        int cn = warp_n * 32 + nf * 8 + 2 * tig;
        bn0[nf] = g_b2p[cn]; bn1[nf] = g_b2p[cn + 1];
    }
    #pragma unroll
    for (int mf = 0; mf < 4; mf++) {
        #pragma unroll
        for (int half = 0; half < 2; half++) {
            int gr = row0 + warp_m * 64 + mf * 16 + g + half * 8;
            if (gr < M) {
                #pragma unroll
                for (int nf = 0; nf < 4; nf++) {
                    int cn = warp_n * 32 + nf * 8 + 2 * tig;
                    float2 fv = *(const float2*)&feats[(long)gr * DIM + cn];
                    float v0 = c[mf][nf][half * 2 + 0] + bn0[nf] + fv.x;
                    float v1 = c[mf][nf][half * 2 + 1] + bn1[nf] + fv.y;
                    *(float2*)&out[(long)gr * DIM + cn] = make_float2(v0, v1);
                }
            }
        }
    }
}

// ============================================================
extern "C" void kernel_launch(void* const* d_in, const int* in_sizes, int n_in,
                              void* d_out, int out_size) {
    const float* feats = (const float*)d_in[0];
    const int*   nb    = (const int*)d_in[1];
    const float* dw_w  = (const float*)d_in[2];
    const float* dw_b  = (const float*)d_in[3];
    const float* ln_g  = (const float*)d_in[4];
    const float* ln_b  = (const float*)d_in[5];
    const float* w1    = (const float*)d_in[6];
    const float* b1    = (const float*)d_in[7];
    const float* grn_g = (const float*)d_in[8];
    const float* grn_b = (const float*)d_in[9];
    const float* w2    = (const float*)d_in[10];
    const float* b2    = (const float*)d_in[11];
    float* out = (float*)d_out;
    int M = in_sizes[0] / DIM;

    static int s_attr_done = 0;
    if (!s_attr_done) {
        cudaFuncSetAttribute(gemm1_mma, cudaFuncAttributeMaxDynamicSharedMemorySize, SMEM_BYTES);
        cudaFuncSetAttribute(gemm2_mma, cudaFuncAttributeMaxDynamicSharedMemorySize, SMEM_BYTES);
        s_attr_done = 1;
    }

    zero_gsq_kernel<<<1, HID>>>();
    w1h_kernel<<<dim3(HID / 32, DIM / 32), dim3(32, 8)>>>(w1);
    dw_ln_kernel<<<M, 128>>>(feats, nb, dw_w, dw_b, ln_g, ln_b, M);

    dim3 g1((M + 127) / 128, HID / 128);
    gemm1_mma<<<g1, 256, SMEM_BYTES>>>(b1, M);

    grn_kernel<<<1, HID>>>(grn_g);
    w2h_kernel<<<dim3(DIM / 32, HID / 32), dim3(32, 8)>>>(w2);
    bias2p_kernel<<<1, HID>>>(w2, b2, grn_b);

    gemm2_mma<<<(M + 127) / 128, 256, SMEM_BYTES>>>(feats, out, M);
}

// round 17
// speedup vs baseline: 2.2344x; 1.0164x over previous
#include <cuda_runtime.h>
#include <cuda_fp16.h>
#include <math.h>
#include <cstdint>

#define NSMAX 100000
#define DIM   128
#define HID   512
#define KVOL  343

// ---- scratch (__device__ globals; no allocation allowed) ----
__device__ __half g_xln[(size_t)NSMAX * DIM];  // LayerNorm output (fp16) [N,128]
__device__ __half g_h[(size_t)NSMAX * HID];    // GELU(x@w1+b1)   (fp16) [N,512]
__device__ __half g_w1h[(size_t)HID * DIM];    // w1^T fp16, n-major [512][128]
__device__ __half g_w2h[(size_t)DIM * HID];    // (diag(s)w2)^T fp16 [128][512]
__device__ float  g_b2p[DIM];                  // b2 + grn_b @ w2
__device__ float  g_gsq[HID];                  // per-channel sum(h^2), fp32
__device__ float  g_scale[HID];                // GRN scale: grn_g*nx + 1

// SMEM halfword stride 136 -> row stride 272 B -> ldmatrix phases conflict-free
#define ASTH 136
#define ROWB (ASTH * 2)                        // 272 bytes per tile row
#define SMEM_BYTES (2 * 128 * ASTH * 2)        // A + B tiles, fp16 = 69632 B

__device__ __forceinline__ void mma_f16(float* c, const uint32_t* a, const uint32_t* b) {
    asm volatile(
        "mma.sync.aligned.m16n8k16.row.col.f32.f16.f16.f32 "
        "{%0,%1,%2,%3}, {%4,%5,%6,%7}, {%8,%9}, {%0,%1,%2,%3};"
        : "+f"(c[0]), "+f"(c[1]), "+f"(c[2]), "+f"(c[3])
        : "r"(a[0]), "r"(a[1]), "r"(a[2]), "r"(a[3]), "r"(b[0]), "r"(b[1]));
}

__device__ __forceinline__ void ldsm_x4(uint32_t& r0, uint32_t& r1, uint32_t& r2, uint32_t& r3,
                                        uint32_t addr) {
    asm volatile("ldmatrix.sync.aligned.m8n8.x4.shared.b16 {%0,%1,%2,%3}, [%4];"
                 : "=r"(r0), "=r"(r1), "=r"(r2), "=r"(r3) : "r"(addr));
}

// ============================================================
// 0. zero GRN accumulator
// ============================================================
__global__ void zero_gsq_kernel() { g_gsq[threadIdx.x] = 0.f; }

// ============================================================
// 0b. w1 -> fp16 n-major transpose: g_w1h[n][k] = w1[k][n]
// ============================================================
__global__ void w1h_kernel(const float* __restrict__ w1) {
    __shared__ float s[32][33];
    int n0 = blockIdx.x * 32, k0 = blockIdx.y * 32;
    int tx = threadIdx.x, ty = threadIdx.y;  // (32,8)
    #pragma unroll
    for (int j = 0; j < 32; j += 8) s[ty + j][tx] = w1[(long)(k0 + ty + j) * HID + n0 + tx];
    __syncthreads();
    #pragma unroll
    for (int j = 0; j < 32; j += 8)
        g_w1h[(long)(n0 + ty + j) * DIM + k0 + tx] = __float2half_rn(s[tx][ty + j]);
}

// ============================================================
// 1. sparse depthwise conv + LayerNorm (validated) -> fp16 out
// ============================================================
__global__ __launch_bounds__(128)
void dw_ln_kernel(const float* __restrict__ feats, const int* __restrict__ nb,
                  const float* __restrict__ dw_w, const float* __restrict__ dw_b,
                  const float* __restrict__ ln_g, const float* __restrict__ ln_b, int M) {
    int i = blockIdx.x, tid = threadIdx.x;
    int lane = tid & 31, wid = tid >> 5;
    __shared__ int s_idx[KVOL], s_k[KVOL], s_wsum[4], s_total;
    __shared__ float red[8];

    long base = (long)i * KVOL;
    int myi[3], myk[3], cnt = 0;
    #pragma unroll
    for (int r = 0; r < 3; r++) {
        int j = tid + r * 128;
        if (j < KVOL) {
            int idx = nb[base + j];
            if (idx < M) { myi[cnt] = idx; myk[cnt] = j; cnt++; }
        }
    }
    int x = cnt;
    #pragma unroll
    for (int o = 1; o < 32; o <<= 1) {
        int y = __shfl_up_sync(0xffffffffu, x, o);
        if (lane >= o) x += y;
    }
    if (lane == 31) s_wsum[wid] = x;
    __syncthreads();
    int wbase = 0;
    for (int w = 0; w < wid; w++) wbase += s_wsum[w];
    int excl = wbase + x - cnt;
    for (int q = 0; q < cnt; q++) { s_idx[excl + q] = myi[q]; s_k[excl + q] = myk[q]; }
    if (tid == 127) s_total = excl + cnt;
    __syncthreads();

    float acc = 0.f;
    int total = s_total;
    for (int p = 0; p < total; p++)
        acc += feats[(long)s_idx[p] * DIM + tid] * dw_w[s_k[p] * DIM + tid];
    acc += dw_b[tid];

    float s = acc, s2 = acc * acc;
    #pragma unroll
    for (int o = 16; o; o >>= 1) {
        s  += __shfl_xor_sync(0xffffffffu, s, o);
        s2 += __shfl_xor_sync(0xffffffffu, s2, o);
    }
    if (lane == 0) { red[wid] = s; red[4 + wid] = s2; }
    __syncthreads();
    if (tid == 0) {
        float ts = red[0] + red[1] + red[2] + red[3];
        float t2 = red[4] + red[5] + red[6] + red[7];
        float mu = ts * (1.f / DIM);
        float var = t2 * (1.f / DIM) - mu * mu;
        red[0] = mu; red[1] = rsqrtf(var + 1e-6f);
    }
    __syncthreads();
    float mu = red[0], rs = red[1];
    g_xln[(long)i * DIM + tid] = __float2half_rn((acc - mu) * rs * ln_g[tid] + ln_b[tid]);
}

// ============================================================
// 2. GEMM1 (mma.sync f16 + ldmatrix): h = gelu(xln @ w1 + b1)
// ============================================================
__global__ __launch_bounds__(256, 2)
void gemm1_mma(const float* __restrict__ b1, int M) {
    extern __shared__ __half sh[];
    __half* Ah = sh;                    // [128 m][ASTH k]
    __half* Bh = sh + 128 * ASTH;       // [128 n][ASTH k]
    __shared__ float bsum[128];

    int t = threadIdx.x;
    int lane = t & 31, g = lane >> 2, tig = lane & 3;
    int warp_m = (t >> 5) & 1, warp_n = t >> 6;
    int row0 = blockIdx.x * 128, col0 = blockIdx.y * 128;

    // ---- A tile fill (uint4 = 8 halfs, conflict-free) ----
    #pragma unroll
    for (int i = 0; i < 8; i++) {
        int idx = t + i * 256, r = idx >> 4, c8 = idx & 15;
        uint4 u = make_uint4(0u, 0u, 0u, 0u);
        int gr = row0 + r;
        if (gr < M) u = *(const uint4*)&g_xln[(long)gr * DIM + c8 * 8];
        *(uint4*)((uint32_t*)Ah + r * (ASTH / 2) + c8 * 4) = u;
    }
    // ---- B tile fill: rows of g_w1h ----
    #pragma unroll
    for (int i = 0; i < 8; i++) {
        int idx = t + i * 256, n = idx >> 4, c8 = idx & 15;
        uint4 u = *(const uint4*)&g_w1h[(long)(col0 + n) * DIM + c8 * 8];
        *(uint4*)((uint32_t*)Bh + n * (ASTH / 2) + c8 * 4) = u;
    }
    __syncthreads();

    // ldmatrix base addresses (byte, shared space)
    uint32_t a_sm = (uint32_t)__cvta_generic_to_shared(Ah);
    uint32_t b_sm = (uint32_t)__cvta_generic_to_shared(Bh);
    // A: lane -> row m = warp_m*64 + (lane&15), k-half add = (lane>>4)*8
    uint32_t a_base = a_sm + (uint32_t)(warp_m * 64 + (lane & 15)) * ROWB + ((lane >> 4) * 8) * 2;
    // B: lane -> row n = warp_n*32 + (lane&7) + (lane>>4)*8, k-half add = ((lane>>3)&1)*8
    uint32_t b_base = b_sm + (uint32_t)(warp_n * 32 + (lane & 7) + (lane >> 4) * 8) * ROWB
                    + (((lane >> 3) & 1) * 8) * 2;

    float c[4][4][4];
    #pragma unroll
    for (int mf = 0; mf < 4; mf++)
        #pragma unroll
        for (int nf = 0; nf < 4; nf++)
            #pragma unroll
            for (int j = 0; j < 4; j++) c[mf][nf][j] = 0.f;

    #pragma unroll
    for (int ks = 0; ks < 8; ks++) {
        uint32_t a[4][4], b[4][2];
        #pragma unroll
        for (int mf = 0; mf < 4; mf++)
            ldsm_x4(a[mf][0], a[mf][1], a[mf][2], a[mf][3],
                    a_base + (uint32_t)mf * (16 * ROWB) + ks * 32);
        ldsm_x4(b[0][0], b[0][1], b[1][0], b[1][1], b_base + ks * 32);
        ldsm_x4(b[2][0], b[2][1], b[3][0], b[3][1], b_base + 16 * ROWB + ks * 32);
        #pragma unroll
        for (int mf = 0; mf < 4; mf++)
            #pragma unroll
            for (int nf = 0; nf < 4; nf++)
                mma_f16(c[mf][nf], a[mf], b[nf]);
    }

    // ---- epilogue: bias + exact GELU, store fp16 h, accumulate sum(h^2) ----
    float bn0[4], bn1[4], ss0[4], ss1[4];
    #pragma unroll
    for (int nf = 0; nf < 4; nf++) {
        int cn = col0 + warp_n * 32 + nf * 8 + 2 * tig;
        bn0[nf] = b1[cn]; bn1[nf] = b1[cn + 1];
        ss0[nf] = 0.f;    ss1[nf] = 0.f;
    }
    #pragma unroll
    for (int mf = 0; mf < 4; mf++) {
        #pragma unroll
        for (int half = 0; half < 2; half++) {
            int gr = row0 + warp_m * 64 + mf * 16 + g + half * 8;
            if (gr < M) {
                #pragma unroll
                for (int nf = 0; nf < 4; nf++) {
                    int cn = col0 + warp_n * 32 + nf * 8 + 2 * tig;
                    float v0 = c[mf][nf][half * 2 + 0] + bn0[nf];
                    float v1 = c[mf][nf][half * 2 + 1] + bn1[nf];
                    float h0 = 0.5f * v0 * (1.f + erff(v0 * 0.70710678118654752f));
                    float h1 = 0.5f * v1 * (1.f + erff(v1 * 0.70710678118654752f));
                    *(__half2*)&g_h[(long)gr * HID + cn] = __floats2half2_rn(h0, h1);
                    ss0[nf] += h0 * h0;
                    ss1[nf] += h1 * h1;
                }
            }
        }
    }
    if (t < 128) bsum[t] = 0.f;
    __syncthreads();
    #pragma unroll
    for (int nf = 0; nf < 4; nf++) {
        int cn = warp_n * 32 + nf * 8 + 2 * tig;
        atomicAdd(&bsum[cn], ss0[nf]);
        atomicAdd(&bsum[cn + 1], ss1[nf]);
    }
    __syncthreads();
    if (t < 128) atomicAdd(&g_gsq[col0 + t], bsum[t]);
}

// ============================================================
// 3. GRN scale: s[c] = grn_g[c] * (gx / (mean(gx)+eps)) + 1
// ============================================================
__global__ void grn_kernel(const float* __restrict__ grn_g) {
    __shared__ float red[16];
    int c = threadIdx.x;  // 512
    float gx = sqrtf(g_gsq[c]);
    float s = gx;
    #pragma unroll
    for (int o = 16; o; o >>= 1) s += __shfl_xor_sync(0xffffffffu, s, o);
    if ((c & 31) == 0) red[c >> 5] = s;
    __syncthreads();
    if (c == 0) {
        float tsum = 0.f;
        for (int w = 0; w < 16; w++) tsum += red[w];
        red[0] = tsum * (1.f / HID);
    }
    __syncthreads();
    float mean = red[0];
    g_scale[c] = grn_g[c] * (gx / (mean + 1e-6f)) + 1.f;
}

// ============================================================
// 3b. w2 -> fp16 n-major with GRN scale: g_w2h[n][k] = w2[k][n]*s[k]
// ============================================================
__global__ void w2h_kernel(const float* __restrict__ w2) {
    __shared__ float s[32][33];
    int n0 = blockIdx.x * 32, k0 = blockIdx.y * 32;
    int tx = threadIdx.x, ty = threadIdx.y;  // (32,8)
    #pragma unroll
    for (int j = 0; j < 32; j += 8) s[ty + j][tx] = w2[(long)(k0 + ty + j) * DIM + n0 + tx];
    __syncthreads();
    #pragma unroll
    for (int j = 0; j < 32; j += 8)
        g_w2h[(long)(n0 + ty + j) * HID + k0 + tx] =
            __float2half_rn(s[tx][ty + j] * g_scale[k0 + tx]);
}

// ============================================================
// 3c. bias2' = b2 + grn_b @ w2
// ============================================================
__global__ void bias2p_kernel(const float* __restrict__ w2, const float* __restrict__ b2,
                              const float* __restrict__ grn_b) {
    __shared__ float part[4][DIM];
    int t = threadIdx.x;  // 512
    int j = t & 127, p = t >> 7;
    float acc = 0.f;
    #pragma unroll 4
    for (int k = p * 128; k < (p + 1) * 128; k++) acc += grn_b[k] * w2[k * DIM + j];
    part[p][j] = acc;
    __syncthreads();
    if (t < 128) g_b2p[t] = b2[t] + part[0][t] + part[1][t] + part[2][t] + part[3][t];
}

// ============================================================
// 4. GEMM2 (mma.sync f16 + ldmatrix): out = h @ (diag(s)w2) + bias2' + feats
// ============================================================
__global__ __launch_bounds__(256, 2)
void gemm2_mma(const float* __restrict__ feats, float* __restrict__ out, int M) {
    extern __shared__ __half sh[];
    __half* Ah = sh;
    __half* Bh = sh + 128 * ASTH;

    int t = threadIdx.x;
    int lane = t & 31, g = lane >> 2, tig = lane & 3;
    int warp_m = (t >> 5) & 1, warp_n = t >> 6;
    int row0 = blockIdx.x * 128;

    uint32_t a_sm = (uint32_t)__cvta_generic_to_shared(Ah);
    uint32_t b_sm = (uint32_t)__cvta_generic_to_shared(Bh);
    uint32_t a_base = a_sm + (uint32_t)(warp_m * 64 + (lane & 15)) * ROWB + ((lane >> 4) * 8) * 2;
    uint32_t b_base = b_sm + (uint32_t)(warp_n * 32 + (lane & 7) + (lane >> 4) * 8) * ROWB
                    + (((lane >> 3) & 1) * 8) * 2;

    float c[4][4][4];
    #pragma unroll
    for (int mf = 0; mf < 4; mf++)
        #pragma unroll
        for (int nf = 0; nf < 4; nf++)
            #pragma unroll
            for (int j = 0; j < 4; j++) c[mf][nf][j] = 0.f;

    for (int cc = 0; cc < 4; cc++) {
        int k0 = cc * 128;
        if (cc > 0) __syncthreads();
        // A chunk: h rows (fp16 uint4 copy)
        #pragma unroll
        for (int i = 0; i < 8; i++) {
            int idx = t + i * 256, r = idx >> 4, c8 = idx & 15;
            uint4 u = make_uint4(0u, 0u, 0u, 0u);
            int gr = row0 + r;
            if (gr < M) u = *(const uint4*)&g_h[(long)gr * HID + k0 + c8 * 8];
            *(uint4*)((uint32_t*)Ah + r * (ASTH / 2) + c8 * 4) = u;
        }
        // B chunk: rows of g_w2h
        #pragma unroll
        for (int i = 0; i < 8; i++) {
            int idx = t + i * 256, n = idx >> 4, c8 = idx & 15;
            uint4 u = *(const uint4*)&g_w2h[(long)n * HID + k0 + c8 * 8];
            *(uint4*)((uint32_t*)Bh + n * (ASTH / 2) + c8 * 4) = u;
        }
        __syncthreads();

        #pragma unroll
        for (int ks = 0; ks < 8; ks++) {
            uint32_t a[4][4], b[4][2];
            #pragma unroll
            for (int mf = 0; mf < 4; mf++)
                ldsm_x4(a[mf][0], a[mf][1], a[mf][2], a[mf][3],
                        a_base + (uint32_t)mf * (16 * ROWB) + ks * 32);
            ldsm_x4(b[0][0], b[0][1], b[1][0], b[1][1], b_base + ks * 32);
            ldsm_x4(b[2][0], b[2][1], b[3][0], b[3][1], b_base + 16 * ROWB + ks * 32);
            #pragma unroll
            for (int mf = 0; mf < 4; mf++)
                #pragma unroll
                for (int nf = 0; nf < 4; nf++)
                    mma_f16(c[mf][nf], a[mf], b[nf]);
        }
    }

    // ---- epilogue: + bias2' + residual feats ----
    float bn0[4], bn1[4];
    #pragma unroll
    for (int nf = 0; nf < 4; nf++) {
        int cn = warp_n * 32 + nf * 8 + 2 * tig;
        bn0[nf] = g_b2p[cn]; bn1[nf] = g_b2p[cn + 1];
    }
    #pragma unroll
    for (int mf = 0; mf < 4; mf++) {
        #pragma unroll
        for (int half = 0; half < 2; half++) {
            int gr = row0 + warp_m * 64 + mf * 16 + g + half * 8;
            if (gr < M) {
                #pragma unroll
                for (int nf = 0; nf < 4; nf++) {
                    int cn = warp_n * 32 + nf * 8 + 2 * tig;
                    float2 fv = *(const float2*)&feats[(long)gr * DIM + cn];
                    float v0 = c[mf][nf][half * 2 + 0] + bn0[nf] + fv.x;
                    float v1 = c[mf][nf][half * 2 + 1] + bn1[nf] + fv.y;
                    *(float2*)&out[(long)gr * DIM + cn] = make_float2(v0, v1);
                }
            }
        }
    }
}

// ============================================================
extern "C" void kernel_launch(void* const* d_in, const int* in_sizes, int n_in,
                              void* d_out, int out_size) {
    const float* feats = (const float*)d_in[0];
    const int*   nb    = (const int*)d_in[1];
    const float* dw_w  = (const float*)d_in[2];
    const float* dw_b  = (const float*)d_in[3];
    const float* ln_g  = (const float*)d_in[4];
    const float* ln_b  = (const float*)d_in[5];
    const float* w1    = (const float*)d_in[6];
    const float* b1    = (const float*)d_in[7];
    const float* grn_g = (const float*)d_in[8];
    const float* grn_b = (const float*)d_in[9];
    const float* w2    = (const float*)d_in[10];
    const float* b2    = (const float*)d_in[11];
    float* out = (float*)d_out;
    int M = in_sizes[0] / DIM;

    static int s_attr_done = 0;
    if (!s_attr_done) {
        cudaFuncSetAttribute(gemm1_mma, cudaFuncAttributeMaxDynamicSharedMemorySize, SMEM_BYTES);
        cudaFuncSetAttribute(gemm2_mma, cudaFuncAttributeMaxDynamicSharedMemorySize, SMEM_BYTES);
        s_attr_done = 1;
    }

    zero_gsq_kernel<<<1, HID>>>();
    w1h_kernel<<<dim3(HID / 32, DIM / 32), dim3(32, 8)>>>(w1);
    dw_ln_kernel<<<M, 128>>>(feats, nb, dw_w, dw_b, ln_g, ln_b, M);

    dim3 g1((M + 127) / 128, HID / 128);
    gemm1_mma<<<g1, 256, SMEM_BYTES>>>(b1, M);

    grn_kernel<<<1, HID>>>(grn_g);
    w2h_kernel<<<dim3(DIM / 32, HID / 32), dim3(32, 8)>>>(w2);
    bias2p_kernel<<<1, HID>>>(w2, b2, grn_b);

    gemm2_mma<<<(M + 127) / 128, 256, SMEM_BYTES>>>(feats, out, M);
}